// round 13
// baseline (speedup 1.0000x reference)
#include <cuda_runtime.h>
#include <cuda_fp16.h>

#define NN 4096
#define FD 128
#define MAXNBR 128
#define NTILE 32                 // 4096/128 S-tiles per dim
#define NTRI  528                // NTILE*(NTILE+1)/2 upper-tri tiles
#define NBLD  1024               // build blocks (4 rows each)
#define NGRID 1584               // 3*NTRI; S at b%3==0, build at the rest

// Scratch (device globals; no cudaMalloc allowed). Hot set = 33 MB, L2-resident.
__device__ __half         g_Sh[(size_t)NN * NN];       // 32 MB fp16 S = exp(f^T C f)
__device__ unsigned short g_idx[(size_t)NN * MAXNBR];  // front/back packed lists
__device__ int            g_cnt0[NN];                  // front-segment count
__device__ int            g_cnt1[NN];                  // back-segment count

// fast exp on the FMA pipe (degree-7 poly of 2^g on [-0.5,0.5]); rel err ~1e-8
__device__ __forceinline__ float fexp(float x) {
    float t = x * 1.4426950408889634f;
    int   ni = __float2int_rn(t);
    float g = t - (float)ni;
    float p =           1.5252734e-5f;
    p = fmaf(p, g,      1.5403530e-4f);
    p = fmaf(p, g,      1.3333558e-3f);
    p = fmaf(p, g,      9.6181291e-3f);
    p = fmaf(p, g,      5.5504109e-2f);
    p = fmaf(p, g,      2.4022651e-1f);
    p = fmaf(p, g,      6.9314718e-1f);
    p = fmaf(p, g,      1.0f);
    return p * __int_as_float((ni + 127) << 23);
}

__device__ __forceinline__ unsigned tf32_rna(float x) {
    unsigned r;
    asm("cvt.rna.tf32.f32 %0, %1;" : "=r"(r) : "f"(x));
    return r;
}

__device__ __forceinline__ void mma_16n8k8(float d[4], const unsigned a[4],
                                           const unsigned b[2]) {
    asm volatile(
        "mma.sync.aligned.m16n8k8.row.col.f32.tf32.tf32.f32 "
        "{%0,%1,%2,%3}, {%4,%5,%6,%7}, {%8,%9}, {%0,%1,%2,%3};"
        : "+f"(d[0]), "+f"(d[1]), "+f"(d[2]), "+f"(d[3])
        : "r"(a[0]), "r"(a[1]), "r"(a[2]), "r"(a[3]), "r"(b[0]), "r"(b[1]));
}

// ---------------------------------------------------------------------------
// build part: neighbor-list scan for 4 rows (2 warps/row, front/back halves),
// ballot fast-path on all-zero float4 groups, MLP 8, evict-first loads
// (single-use adjacency stream must not pollute L2 while S-tiles write Sh).
// ---------------------------------------------------------------------------
__device__ void build_rows(const float* __restrict__ nbr, int blk) {
    const int warp = threadIdx.x >> 5;        // 0..7
    const int lane = threadIdx.x & 31;
    const int rloc = warp >> 1;
    const int h    = warp & 1;
    const int j    = blk * 4 + rloc;
    const float4* row = (const float4*)(nbr + (size_t)j * NN) + h * 512;
    unsigned short* lst = g_idx + (size_t)j * MAXNBR;
    const unsigned lt = (1u << lane) - 1u;
    const int colbase = h * 2048;

    int base = 0;
    #pragma unroll 1
    for (int step = 0; step < 2; ++step) {
        float4 v[8];
        #pragma unroll
        for (int u = 0; u < 8; ++u)
            v[u] = __ldcs(&row[(step * 8 + u) * 32 + lane]);  // 8 loads in flight

        #pragma unroll
        for (int u = 0; u < 8; ++u) {
            bool nz = (v[u].x != 0.0f) | (v[u].y != 0.0f) |
                      (v[u].z != 0.0f) | (v[u].w != 0.0f);
            unsigned any = __ballot_sync(0xFFFFFFFFu, nz);
            if (any == 0u) continue;                     // warp-uniform skip

            int col = colbase + ((step * 8 + u) * 32 + lane) * 4;
            unsigned m0 = __ballot_sync(0xFFFFFFFFu, v[u].x != 0.0f);
            unsigned m1 = __ballot_sync(0xFFFFFFFFu, v[u].y != 0.0f);
            unsigned m2 = __ballot_sync(0xFFFFFFFFu, v[u].z != 0.0f);
            unsigned m3 = __ballot_sync(0xFFFFFFFFu, v[u].w != 0.0f);
            int t0 = __popc(m0), t1 = __popc(m1), t2 = __popc(m2), t3 = __popc(m3);
            int p0 = base + __popc(m0 & lt);
            int p1 = base + t0 + __popc(m1 & lt);
            int p2 = base + t0 + t1 + __popc(m2 & lt);
            int p3 = base + t0 + t1 + t2 + __popc(m3 & lt);
            if (h == 0) {
                if ((m0 >> lane) & 1 && p0 < MAXNBR) lst[p0] = (unsigned short)(col + 0);
                if ((m1 >> lane) & 1 && p1 < MAXNBR) lst[p1] = (unsigned short)(col + 1);
                if ((m2 >> lane) & 1 && p2 < MAXNBR) lst[p2] = (unsigned short)(col + 2);
                if ((m3 >> lane) & 1 && p3 < MAXNBR) lst[p3] = (unsigned short)(col + 3);
            } else {
                if ((m0 >> lane) & 1 && p0 < MAXNBR) lst[MAXNBR - 1 - p0] = (unsigned short)(col + 0);
                if ((m1 >> lane) & 1 && p1 < MAXNBR) lst[MAXNBR - 1 - p1] = (unsigned short)(col + 1);
                if ((m2 >> lane) & 1 && p2 < MAXNBR) lst[MAXNBR - 1 - p2] = (unsigned short)(col + 2);
                if ((m3 >> lane) & 1 && p3 < MAXNBR) lst[MAXNBR - 1 - p3] = (unsigned short)(col + 3);
            }
            base += t0 + t1 + t2 + t3;
        }
    }
    if (lane == 0) {
        int c = min(base, MAXNBR);
        if (h == 0) g_cnt0[j] = c; else g_cnt1[j] = c;
    }
}

// ---------------------------------------------------------------------------
// Kernel A (FUSED build + S), INTERLEAVED: S-tile at b%3==0 (528 exactly),
// build at the remaining slots (1056 slots, first 1024 active). Every wave
// mixes tensor-bound S CTAs with DRAM-bound build CTAs.
// ---------------------------------------------------------------------------
__global__ void __launch_bounds__(256, 2)
build_and_S_kernel(const float* __restrict__ f,
                   const float* __restrict__ nbr,
                   const float* __restrict__ wq,
                   const float* __restrict__ wk) {
    const int b = blockIdx.x;
    if (b % 3 != 0) {                   // ---- build partition ----
        int nb = b - (b + 2) / 3;       // dense index among non-S blocks
        if (nb < NBLD) build_rows(nbr, nb);
        return;
    }

    // ---- S partition: map linear triangular index -> (ti, tj), tj >= ti ----
    const int t = b / 3;
    int ti = (int)((65.0f - sqrtf(4225.0f - 8.0f * (float)t)) * 0.5f);
    while (ti * (65 - ti) / 2 > t) --ti;
    while ((ti + 1) * (64 - ti) / 2 <= t) ++ti;
    const int tj = ti + (t - ti * (65 - ti) / 2);

    __shared__ float s_raw[2 * 32 * 132];   // As[32][132] | Bs[32][132] (33.8 KB)
    __shared__ float cs[FD];
    float* As = s_raw;
    float* Bs = s_raw + 32 * 132;

    const int tid  = threadIdx.x;
    const int warp = tid >> 5;
    const int lane = tid & 31;
    const int gID  = lane >> 2;
    const int tig  = lane & 3;
    const int wr   = warp >> 2;
    const int wc   = warp & 3;
    const int iw   = wr * 64;
    const int jw   = wc * 32;
    const int i0   = ti * 128;
    const int j0   = tj * 128;

    if (tid < FD) cs[tid] = wq[tid] * wk[tid];
    __syncthreads();

    float acc[4][4][4] = {};

    #pragma unroll 1
    for (int kb = 0; kb < 4; ++kb) {          // 4 chunks of 32 k-slices
        #pragma unroll
        for (int r = 0; r < 4; ++r) {
            int e  = tid + r * 256;
            int d2 = e >> 5;
            int c4 = (e & 31) * 4;
            int d  = kb * 32 + d2;
            float cc = cs[d];
            float4 va = *(const float4*)&f[(size_t)d * NN + i0 + c4];
            unsigned* ap = (unsigned*)&As[d2 * 132 + c4];
            ap[0] = tf32_rna(va.x * cc); ap[1] = tf32_rna(va.y * cc);
            ap[2] = tf32_rna(va.z * cc); ap[3] = tf32_rna(va.w * cc);
            float4 vb = *(const float4*)&f[(size_t)d * NN + j0 + c4];
            unsigned* bp = (unsigned*)&Bs[d2 * 132 + c4];
            bp[0] = tf32_rna(vb.x); bp[1] = tf32_rna(vb.y);
            bp[2] = tf32_rna(vb.z); bp[3] = tf32_rna(vb.w);
        }
        __syncthreads();

        #pragma unroll
        for (int k8 = 0; k8 < 4; ++k8) {
            const int kr0 = k8 * 8 + tig;
            unsigned a[4][4];
            #pragma unroll
            for (int mi = 0; mi < 4; ++mi) {
                int ib = iw + mi * 16 + gID;
                a[mi][0] = ((unsigned*)As)[(kr0    ) * 132 + ib];
                a[mi][1] = ((unsigned*)As)[(kr0    ) * 132 + ib + 8];
                a[mi][2] = ((unsigned*)As)[(kr0 + 4) * 132 + ib];
                a[mi][3] = ((unsigned*)As)[(kr0 + 4) * 132 + ib + 8];
            }
            unsigned b2[4][2];
            #pragma unroll
            for (int ni = 0; ni < 4; ++ni) {
                int jb = jw + ni * 8 + gID;
                b2[ni][0] = ((unsigned*)Bs)[(kr0    ) * 132 + jb];
                b2[ni][1] = ((unsigned*)Bs)[(kr0 + 4) * 132 + jb];
            }
            #pragma unroll
            for (int mi = 0; mi < 4; ++mi)
                #pragma unroll
                for (int ni = 0; ni < 4; ++ni)
                    mma_16n8k8(acc[mi][ni], a[mi], b2[ni]);
        }
        __syncthreads();
    }

    #pragma unroll
    for (int mi = 0; mi < 4; ++mi)
        #pragma unroll
        for (int ni = 0; ni < 4; ++ni)
            #pragma unroll
            for (int r = 0; r < 4; ++r)
                acc[mi][ni][r] = fexp(acc[mi][ni][r]);

    // primary tile store: fp16 half2 per fragment pair
    #pragma unroll
    for (int mi = 0; mi < 4; ++mi) {
        #pragma unroll
        for (int h = 0; h < 2; ++h) {
            int row = i0 + iw + mi * 16 + gID + h * 8;
            size_t rbase = (size_t)row * NN + j0;
            #pragma unroll
            for (int ni = 0; ni < 4; ++ni) {
                int col = jw + ni * 8 + 2 * tig;
                __half2 hh = __floats2half2_rn(acc[mi][ni][h * 2 + 0],
                                               acc[mi][ni][h * 2 + 1]);
                *(unsigned*)&g_Sh[rbase + col] = *(unsigned*)&hh;
            }
        }
    }

    // mirror tile (ti != tj): stage 32 tile-cols at a time
    if (ti != tj) {
        float* st = s_raw;   // st[c_local 0..31][row 0..127], stride 132
        #pragma unroll 1
        for (int q = 0; q < 4; ++q) {
            __syncthreads();
            if (wc == q) {
                #pragma unroll
                for (int mi = 0; mi < 4; ++mi)
                    #pragma unroll
                    for (int h = 0; h < 2; ++h) {
                        int rt = iw + mi * 16 + gID + h * 8;
                        #pragma unroll
                        for (int ni = 0; ni < 4; ++ni) {
                            int cl = ni * 8 + 2 * tig;
                            st[(cl + 0) * 132 + rt] = acc[mi][ni][h * 2 + 0];
                            st[(cl + 1) * 132 + rt] = acc[mi][ni][h * 2 + 1];
                        }
                    }
            }
            __syncthreads();
            #pragma unroll
            for (int w = 0; w < 4; ++w) {
                int e4 = tid + w * 256;
                int jl = e4 >> 5;
                int i4 = (e4 & 31) * 4;
                float4 v = *(float4*)&st[jl * 132 + i4];
                size_t rbase = (size_t)(j0 + q * 32 + jl) * NN + i0;
                __half2 h0 = __floats2half2_rn(v.x, v.y);
                __half2 h1 = __floats2half2_rn(v.z, v.w);
                uint2 u = make_uint2(*(unsigned*)&h0, *(unsigned*)&h1);
                *(uint2*)&g_Sh[rbase + i4] = u;
            }
        }
    }
}

// ---------------------------------------------------------------------------
// Kernel B (FUSED gather + divide + transposed write):
// CTA = 32 j's x 128 cols, 512 threads; thread = (1 j, 8 cols).
// Two clean segment loops + two-level fp16 hadd2 tree.
// Grid: x = j-blocks (128), y = col-chunks (32) — a wave covers all j's of
// few column slices, keeping the active L2 gather footprint small.
// ---------------------------------------------------------------------------
__device__ __forceinline__ void addquad(float* acc, const uint4& a, const uint4& b,
                                        const uint4& c, const uint4& d) {
    const __half2* ha = (const __half2*)&a;
    const __half2* hb = (const __half2*)&b;
    const __half2* hc = (const __half2*)&c;
    const __half2* hd = (const __half2*)&d;
    #pragma unroll
    for (int i = 0; i < 4; ++i) {
        __half2 q = __hadd2(__hadd2(ha[i], hb[i]), __hadd2(hc[i], hd[i]));
        float2 p = __half22float2(q);
        acc[2 * i + 0] += p.x;
        acc[2 * i + 1] += p.y;
    }
}
__device__ __forceinline__ void addpair(float* acc, const uint4& x, const uint4& y) {
    const __half2* a = (const __half2*)&x;
    const __half2* b = (const __half2*)&y;
    #pragma unroll
    for (int i = 0; i < 4; ++i) {
        float2 p = __half22float2(__hadd2(a[i], b[i]));
        acc[2 * i + 0] += p.x;
        acc[2 * i + 1] += p.y;
    }
}
__device__ __forceinline__ void addone(float* acc, const uint4& x) {
    const __half2* a = (const __half2*)&x;
    #pragma unroll
    for (int i = 0; i < 4; ++i) {
        float2 p = __half22float2(a[i]);
        acc[2 * i + 0] += p.x;
        acc[2 * i + 1] += p.y;
    }
}

__global__ void __launch_bounds__(512)
fused_T_kernel(float* __restrict__ out) {
    __shared__ unsigned short s_idx[32 * MAXNBR];   // 8 KB
    __shared__ int            s_c0[32];
    __shared__ int            s_c1[32];
    __shared__ float          stage[32 * 129];      // 16.5 KB  [jt][cl]

    const int tid = threadIdx.x;
    const int cg  = tid & 15;
    const int jt  = tid >> 4;
    const int c0  = blockIdx.y * 128;               // col chunk
    const int j0  = blockIdx.x * 32;                // j block

    {
        const uint4* src = (const uint4*)(g_idx + (size_t)j0 * MAXNBR);
        ((uint4*)s_idx)[tid] = src[tid];
        if (tid < 32) { s_c0[tid] = g_cnt0[j0 + tid]; s_c1[tid] = g_cnt1[j0 + tid]; }
    }
    __syncthreads();

    const int j  = j0 + jt;
    const int c8 = c0 + cg * 8;
    const unsigned short* lst = &s_idx[jt * MAXNBR];

    // two physical segments: [0, cnt0) and [MAXNBR - cnt1, MAXNBR)
    int segLo[2], segHi[2];
    segLo[0] = 0;                   segHi[0] = s_c0[jt];
    segLo[1] = MAXNBR - s_c1[jt];   segHi[1] = MAXNBR;

    float acc[8] = {};
    #pragma unroll
    for (int s = 0; s < 2; ++s) {
        int k = segLo[s];
        const int hi = segHi[s];
        for (; k + 8 <= hi; k += 8) {
            uint4 hv[8];
            #pragma unroll
            for (int u = 0; u < 8; ++u)
                hv[u] = *(const uint4*)&g_Sh[(size_t)lst[k + u] * NN + c8];
            addquad(acc, hv[0], hv[1], hv[2], hv[3]);
            addquad(acc, hv[4], hv[5], hv[6], hv[7]);
        }
        for (; k + 4 <= hi; k += 4) {
            uint4 hv[4];
            #pragma unroll
            for (int u = 0; u < 4; ++u)
                hv[u] = *(const uint4*)&g_Sh[(size_t)lst[k + u] * NN + c8];
            addquad(acc, hv[0], hv[1], hv[2], hv[3]);
        }
        for (; k + 2 <= hi; k += 2) {
            uint4 h0 = *(const uint4*)&g_Sh[(size_t)lst[k + 0] * NN + c8];
            uint4 h1 = *(const uint4*)&g_Sh[(size_t)lst[k + 1] * NN + c8];
            addpair(acc, h0, h1);
        }
        if (k < hi) {
            uint4 h = *(const uint4*)&g_Sh[(size_t)lst[k] * NN + c8];
            addone(acc, h);
        }
    }

    // numerator (fp16), divide, stage [jt][cl]
    uint4 nh = *(const uint4*)&g_Sh[(size_t)j * NN + c8];
    float num[8];
    {
        const __half2* a = (const __half2*)&nh;
        #pragma unroll
        for (int i = 0; i < 4; ++i) {
            float2 p = __half22float2(a[i]);
            num[2 * i + 0] = p.x;
            num[2 * i + 1] = p.y;
        }
    }
    float* sp = &stage[jt * 129 + cg * 8];
    #pragma unroll
    for (int q = 0; q < 8; ++q)
        sp[q] = num[q] / acc[q];
    __syncthreads();

    // transposed write: out rows c0+cl (128 rows), 32 contiguous j's each
    #pragma unroll
    for (int w = 0; w < 2; ++w) {
        int e  = tid + w * 512;
        int cl = e >> 3;
        int j4 = (e & 7) * 4;
        float4 v = make_float4(stage[(j4 + 0) * 129 + cl],
                               stage[(j4 + 1) * 129 + cl],
                               stage[(j4 + 2) * 129 + cl],
                               stage[(j4 + 3) * 129 + cl]);
        *(float4*)&out[(size_t)(c0 + cl) * NN + j0 + j4] = v;
    }
}

// ---------------------------------------------------------------------------
extern "C" void kernel_launch(void* const* d_in, const int* in_sizes, int n_in,
                              void* d_out, int out_size) {
    const float* f   = (const float*)d_in[0];   // [128, 4096]
    const float* nbr = (const float*)d_in[1];   // [4096, 4096]
    const float* wq  = (const float*)d_in[2];   // [128]
    const float* wk  = (const float*)d_in[3];   // [128]
    float* out = (float*)d_out;                 // [4096, 4096]

    build_and_S_kernel<<<NGRID, 256>>>(f, nbr, wq, wk);
    fused_T_kernel<<<dim3(NN / 32, NN / 128), 512>>>(out);
}

// round 14
// speedup vs baseline: 1.0568x; 1.0568x over previous
#include <cuda_runtime.h>
#include <cuda_fp16.h>

#define NN 4096
#define FD 128
#define MAXNBR 128
#define NTILE 32                 // 4096/128 S-tiles per dim
#define NTRI  528                // NTILE*(NTILE+1)/2 upper-tri tiles
#define NBLD  1024               // build blocks (4 rows each)

// Scratch (device globals; no cudaMalloc allowed). Hot set = 33 MB, L2-resident.
__device__ __half         g_Sh[(size_t)NN * NN];       // 32 MB fp16 S = exp(f^T C f)
__device__ unsigned short g_idx[(size_t)NN * MAXNBR];  // front/back packed lists
__device__ int            g_cnt0[NN];                  // front-segment count
__device__ int            g_cnt1[NN];                  // back-segment count

// fast exp on the FMA pipe (degree-7 poly of 2^g on [-0.5,0.5]); rel err ~1e-8
__device__ __forceinline__ float fexp(float x) {
    float t = x * 1.4426950408889634f;
    int   ni = __float2int_rn(t);
    float g = t - (float)ni;
    float p =           1.5252734e-5f;
    p = fmaf(p, g,      1.5403530e-4f);
    p = fmaf(p, g,      1.3333558e-3f);
    p = fmaf(p, g,      9.6181291e-3f);
    p = fmaf(p, g,      5.5504109e-2f);
    p = fmaf(p, g,      2.4022651e-1f);
    p = fmaf(p, g,      6.9314718e-1f);
    p = fmaf(p, g,      1.0f);
    return p * __int_as_float((ni + 127) << 23);
}

__device__ __forceinline__ unsigned tf32_rna(float x) {
    unsigned r;
    asm("cvt.rna.tf32.f32 %0, %1;" : "=r"(r) : "f"(x));
    return r;
}

__device__ __forceinline__ void mma_16n8k8(float d[4], const unsigned a[4],
                                           const unsigned b[2]) {
    asm volatile(
        "mma.sync.aligned.m16n8k8.row.col.f32.tf32.tf32.f32 "
        "{%0,%1,%2,%3}, {%4,%5,%6,%7}, {%8,%9}, {%0,%1,%2,%3};"
        : "+f"(d[0]), "+f"(d[1]), "+f"(d[2]), "+f"(d[3])
        : "r"(a[0]), "r"(a[1]), "r"(a[2]), "r"(a[3]), "r"(b[0]), "r"(b[1]));
}

// ---------------------------------------------------------------------------
// build part: neighbor-list scan for 4 rows (2 warps/row, front/back halves),
// ballot fast-path on all-zero float4 groups, MLP 8, plain loads.
// ---------------------------------------------------------------------------
__device__ void build_rows(const float* __restrict__ nbr, int blk) {
    const int warp = threadIdx.x >> 5;        // 0..7
    const int lane = threadIdx.x & 31;
    const int rloc = warp >> 1;
    const int h    = warp & 1;
    const int j    = blk * 4 + rloc;
    const float4* row = (const float4*)(nbr + (size_t)j * NN) + h * 512;
    unsigned short* lst = g_idx + (size_t)j * MAXNBR;
    const unsigned lt = (1u << lane) - 1u;
    const int colbase = h * 2048;

    int base = 0;
    #pragma unroll 1
    for (int step = 0; step < 2; ++step) {
        float4 v[8];
        #pragma unroll
        for (int u = 0; u < 8; ++u)
            v[u] = row[(step * 8 + u) * 32 + lane];      // 8 loads in flight

        #pragma unroll
        for (int u = 0; u < 8; ++u) {
            bool nz = (v[u].x != 0.0f) | (v[u].y != 0.0f) |
                      (v[u].z != 0.0f) | (v[u].w != 0.0f);
            unsigned any = __ballot_sync(0xFFFFFFFFu, nz);
            if (any == 0u) continue;                     // warp-uniform skip

            int col = colbase + ((step * 8 + u) * 32 + lane) * 4;
            unsigned m0 = __ballot_sync(0xFFFFFFFFu, v[u].x != 0.0f);
            unsigned m1 = __ballot_sync(0xFFFFFFFFu, v[u].y != 0.0f);
            unsigned m2 = __ballot_sync(0xFFFFFFFFu, v[u].z != 0.0f);
            unsigned m3 = __ballot_sync(0xFFFFFFFFu, v[u].w != 0.0f);
            int t0 = __popc(m0), t1 = __popc(m1), t2 = __popc(m2), t3 = __popc(m3);
            int p0 = base + __popc(m0 & lt);
            int p1 = base + t0 + __popc(m1 & lt);
            int p2 = base + t0 + t1 + __popc(m2 & lt);
            int p3 = base + t0 + t1 + t2 + __popc(m3 & lt);
            if (h == 0) {
                if ((m0 >> lane) & 1 && p0 < MAXNBR) lst[p0] = (unsigned short)(col + 0);
                if ((m1 >> lane) & 1 && p1 < MAXNBR) lst[p1] = (unsigned short)(col + 1);
                if ((m2 >> lane) & 1 && p2 < MAXNBR) lst[p2] = (unsigned short)(col + 2);
                if ((m3 >> lane) & 1 && p3 < MAXNBR) lst[p3] = (unsigned short)(col + 3);
            } else {
                if ((m0 >> lane) & 1 && p0 < MAXNBR) lst[MAXNBR - 1 - p0] = (unsigned short)(col + 0);
                if ((m1 >> lane) & 1 && p1 < MAXNBR) lst[MAXNBR - 1 - p1] = (unsigned short)(col + 1);
                if ((m2 >> lane) & 1 && p2 < MAXNBR) lst[MAXNBR - 1 - p2] = (unsigned short)(col + 2);
                if ((m3 >> lane) & 1 && p3 < MAXNBR) lst[MAXNBR - 1 - p3] = (unsigned short)(col + 3);
            }
            base += t0 + t1 + t2 + t3;
        }
    }
    if (lane == 0) {
        int c = min(base, MAXNBR);
        if (h == 0) g_cnt0[j] = c; else g_cnt1[j] = c;
    }
}

// ---------------------------------------------------------------------------
// Kernel A (FUSED build + S): blocks [0, NTRI) compute S-tiles (tensor-bound),
// blocks [NTRI, NTRI+NBLD) scan the adjacency (DRAM-bound). S-first ordering:
// build CTAs backfill SMs as early S tiles finish (measured best overlap).
// ---------------------------------------------------------------------------
__global__ void __launch_bounds__(256, 2)
build_and_S_kernel(const float* __restrict__ f,
                   const float* __restrict__ nbr,
                   const float* __restrict__ wq,
                   const float* __restrict__ wk) {
    if (blockIdx.x >= NTRI) {           // ---- build partition ----
        build_rows(nbr, blockIdx.x - NTRI);
        return;
    }

    // ---- S partition: map linear triangular index -> (ti, tj), tj >= ti ----
    const int t = blockIdx.x;
    int ti = (int)((65.0f - sqrtf(4225.0f - 8.0f * (float)t)) * 0.5f);
    while (ti * (65 - ti) / 2 > t) --ti;
    while ((ti + 1) * (64 - ti) / 2 <= t) ++ti;
    const int tj = ti + (t - ti * (65 - ti) / 2);

    __shared__ float s_raw[2 * 32 * 132];   // As[32][132] | Bs[32][132] (33.8 KB)
    __shared__ float cs[FD];
    float* As = s_raw;
    float* Bs = s_raw + 32 * 132;

    const int tid  = threadIdx.x;
    const int warp = tid >> 5;
    const int lane = tid & 31;
    const int gID  = lane >> 2;
    const int tig  = lane & 3;
    const int wr   = warp >> 2;
    const int wc   = warp & 3;
    const int iw   = wr * 64;
    const int jw   = wc * 32;
    const int i0   = ti * 128;
    const int j0   = tj * 128;

    if (tid < FD) cs[tid] = wq[tid] * wk[tid];
    __syncthreads();

    float acc[4][4][4] = {};

    #pragma unroll 1
    for (int kb = 0; kb < 4; ++kb) {          // 4 chunks of 32 k-slices
        #pragma unroll
        for (int r = 0; r < 4; ++r) {
            int e  = tid + r * 256;
            int d2 = e >> 5;
            int c4 = (e & 31) * 4;
            int d  = kb * 32 + d2;
            float cc = cs[d];
            float4 va = *(const float4*)&f[(size_t)d * NN + i0 + c4];
            unsigned* ap = (unsigned*)&As[d2 * 132 + c4];
            ap[0] = tf32_rna(va.x * cc); ap[1] = tf32_rna(va.y * cc);
            ap[2] = tf32_rna(va.z * cc); ap[3] = tf32_rna(va.w * cc);
            float4 vb = *(const float4*)&f[(size_t)d * NN + j0 + c4];
            unsigned* bp = (unsigned*)&Bs[d2 * 132 + c4];
            bp[0] = tf32_rna(vb.x); bp[1] = tf32_rna(vb.y);
            bp[2] = tf32_rna(vb.z); bp[3] = tf32_rna(vb.w);
        }
        __syncthreads();

        #pragma unroll
        for (int k8 = 0; k8 < 4; ++k8) {
            const int kr0 = k8 * 8 + tig;
            unsigned a[4][4];
            #pragma unroll
            for (int mi = 0; mi < 4; ++mi) {
                int ib = iw + mi * 16 + gID;
                a[mi][0] = ((unsigned*)As)[(kr0    ) * 132 + ib];
                a[mi][1] = ((unsigned*)As)[(kr0    ) * 132 + ib + 8];
                a[mi][2] = ((unsigned*)As)[(kr0 + 4) * 132 + ib];
                a[mi][3] = ((unsigned*)As)[(kr0 + 4) * 132 + ib + 8];
            }
            unsigned b[4][2];
            #pragma unroll
            for (int ni = 0; ni < 4; ++ni) {
                int jb = jw + ni * 8 + gID;
                b[ni][0] = ((unsigned*)Bs)[(kr0    ) * 132 + jb];
                b[ni][1] = ((unsigned*)Bs)[(kr0 + 4) * 132 + jb];
            }
            #pragma unroll
            for (int mi = 0; mi < 4; ++mi)
                #pragma unroll
                for (int ni = 0; ni < 4; ++ni)
                    mma_16n8k8(acc[mi][ni], a[mi], b[ni]);
        }
        __syncthreads();
    }

    #pragma unroll
    for (int mi = 0; mi < 4; ++mi)
        #pragma unroll
        for (int ni = 0; ni < 4; ++ni)
            #pragma unroll
            for (int r = 0; r < 4; ++r)
                acc[mi][ni][r] = fexp(acc[mi][ni][r]);

    // primary tile store: fp16 half2 per fragment pair
    #pragma unroll
    for (int mi = 0; mi < 4; ++mi) {
        #pragma unroll
        for (int h = 0; h < 2; ++h) {
            int row = i0 + iw + mi * 16 + gID + h * 8;
            size_t rbase = (size_t)row * NN + j0;
            #pragma unroll
            for (int ni = 0; ni < 4; ++ni) {
                int col = jw + ni * 8 + 2 * tig;
                __half2 hh = __floats2half2_rn(acc[mi][ni][h * 2 + 0],
                                               acc[mi][ni][h * 2 + 1]);
                *(unsigned*)&g_Sh[rbase + col] = *(unsigned*)&hh;
            }
        }
    }

    // mirror tile (ti != tj): stage 32 tile-cols at a time
    if (ti != tj) {
        float* st = s_raw;   // st[c_local 0..31][row 0..127], stride 132
        #pragma unroll 1
        for (int q = 0; q < 4; ++q) {
            __syncthreads();
            if (wc == q) {
                #pragma unroll
                for (int mi = 0; mi < 4; ++mi)
                    #pragma unroll
                    for (int h = 0; h < 2; ++h) {
                        int rt = iw + mi * 16 + gID + h * 8;
                        #pragma unroll
                        for (int ni = 0; ni < 4; ++ni) {
                            int cl = ni * 8 + 2 * tig;
                            st[(cl + 0) * 132 + rt] = acc[mi][ni][h * 2 + 0];
                            st[(cl + 1) * 132 + rt] = acc[mi][ni][h * 2 + 1];
                        }
                    }
            }
            __syncthreads();
            #pragma unroll
            for (int w = 0; w < 4; ++w) {
                int e4 = tid + w * 256;
                int jl = e4 >> 5;
                int i4 = (e4 & 31) * 4;
                float4 v = *(float4*)&st[jl * 132 + i4];
                size_t rbase = (size_t)(j0 + q * 32 + jl) * NN + i0;
                __half2 h0 = __floats2half2_rn(v.x, v.y);
                __half2 h1 = __floats2half2_rn(v.z, v.w);
                uint2 u = make_uint2(*(unsigned*)&h0, *(unsigned*)&h1);
                *(uint2*)&g_Sh[rbase + i4] = u;
            }
        }
    }
}

// ---------------------------------------------------------------------------
// Kernel B (FUSED gather + divide + transposed write):
// CTA = 32 j's x 128 cols, 512 threads; thread = (1 j, 8 cols).
// Two clean segment loops + two-level fp16 hadd2 tree.
// Grid: x = j-blocks (128), y = col-chunks (32) — a wave covers all j's of
// few column slices, keeping the active L2 gather footprint small (measured
// -2.4us vs the swapped order).
// ---------------------------------------------------------------------------
__device__ __forceinline__ void addquad(float* acc, const uint4& a, const uint4& b,
                                        const uint4& c, const uint4& d) {
    const __half2* ha = (const __half2*)&a;
    const __half2* hb = (const __half2*)&b;
    const __half2* hc = (const __half2*)&c;
    const __half2* hd = (const __half2*)&d;
    #pragma unroll
    for (int i = 0; i < 4; ++i) {
        __half2 q = __hadd2(__hadd2(ha[i], hb[i]), __hadd2(hc[i], hd[i]));
        float2 p = __half22float2(q);
        acc[2 * i + 0] += p.x;
        acc[2 * i + 1] += p.y;
    }
}
__device__ __forceinline__ void addpair(float* acc, const uint4& x, const uint4& y) {
    const __half2* a = (const __half2*)&x;
    const __half2* b = (const __half2*)&y;
    #pragma unroll
    for (int i = 0; i < 4; ++i) {
        float2 p = __half22float2(__hadd2(a[i], b[i]));
        acc[2 * i + 0] += p.x;
        acc[2 * i + 1] += p.y;
    }
}
__device__ __forceinline__ void addone(float* acc, const uint4& x) {
    const __half2* a = (const __half2*)&x;
    #pragma unroll
    for (int i = 0; i < 4; ++i) {
        float2 p = __half22float2(a[i]);
        acc[2 * i + 0] += p.x;
        acc[2 * i + 1] += p.y;
    }
}

__global__ void __launch_bounds__(512)
fused_T_kernel(float* __restrict__ out) {
    __shared__ unsigned short s_idx[32 * MAXNBR];   // 8 KB
    __shared__ int            s_c0[32];
    __shared__ int            s_c1[32];
    __shared__ float          stage[32 * 129];      // 16.5 KB  [jt][cl]

    const int tid = threadIdx.x;
    const int cg  = tid & 15;
    const int jt  = tid >> 4;
    const int c0  = blockIdx.y * 128;               // col chunk
    const int j0  = blockIdx.x * 32;                // j block

    {
        const uint4* src = (const uint4*)(g_idx + (size_t)j0 * MAXNBR);
        ((uint4*)s_idx)[tid] = src[tid];
        if (tid < 32) { s_c0[tid] = g_cnt0[j0 + tid]; s_c1[tid] = g_cnt1[j0 + tid]; }
    }
    __syncthreads();

    const int j  = j0 + jt;
    const int c8 = c0 + cg * 8;
    const unsigned short* lst = &s_idx[jt * MAXNBR];

    // two physical segments: [0, cnt0) and [MAXNBR - cnt1, MAXNBR)
    int segLo[2], segHi[2];
    segLo[0] = 0;                   segHi[0] = s_c0[jt];
    segLo[1] = MAXNBR - s_c1[jt];   segHi[1] = MAXNBR;

    float acc[8] = {};
    #pragma unroll
    for (int s = 0; s < 2; ++s) {
        int k = segLo[s];
        const int hi = segHi[s];
        for (; k + 8 <= hi; k += 8) {
            uint4 hv[8];
            #pragma unroll
            for (int u = 0; u < 8; ++u)
                hv[u] = *(const uint4*)&g_Sh[(size_t)lst[k + u] * NN + c8];
            addquad(acc, hv[0], hv[1], hv[2], hv[3]);
            addquad(acc, hv[4], hv[5], hv[6], hv[7]);
        }
        for (; k + 4 <= hi; k += 4) {
            uint4 hv[4];
            #pragma unroll
            for (int u = 0; u < 4; ++u)
                hv[u] = *(const uint4*)&g_Sh[(size_t)lst[k + u] * NN + c8];
            addquad(acc, hv[0], hv[1], hv[2], hv[3]);
        }
        for (; k + 2 <= hi; k += 2) {
            uint4 h0 = *(const uint4*)&g_Sh[(size_t)lst[k + 0] * NN + c8];
            uint4 h1 = *(const uint4*)&g_Sh[(size_t)lst[k + 1] * NN + c8];
            addpair(acc, h0, h1);
        }
        if (k < hi) {
            uint4 h = *(const uint4*)&g_Sh[(size_t)lst[k] * NN + c8];
            addone(acc, h);
        }
    }

    // numerator (fp16), divide, stage [jt][cl]
    uint4 nh = *(const uint4*)&g_Sh[(size_t)j * NN + c8];
    float num[8];
    {
        const __half2* a = (const __half2*)&nh;
        #pragma unroll
        for (int i = 0; i < 4; ++i) {
            float2 p = __half22float2(a[i]);
            num[2 * i + 0] = p.x;
            num[2 * i + 1] = p.y;
        }
    }
    float* sp = &stage[jt * 129 + cg * 8];
    #pragma unroll
    for (int q = 0; q < 8; ++q)
        sp[q] = num[q] / acc[q];
    __syncthreads();

    // transposed write: out rows c0+cl (128 rows), 32 contiguous j's each
    #pragma unroll
    for (int w = 0; w < 2; ++w) {
        int e  = tid + w * 512;
        int cl = e >> 3;
        int j4 = (e & 7) * 4;
        float4 v = make_float4(stage[(j4 + 0) * 129 + cl],
                               stage[(j4 + 1) * 129 + cl],
                               stage[(j4 + 2) * 129 + cl],
                               stage[(j4 + 3) * 129 + cl]);
        *(float4*)&out[(size_t)(c0 + cl) * NN + j0 + j4] = v;
    }
}

// ---------------------------------------------------------------------------
extern "C" void kernel_launch(void* const* d_in, const int* in_sizes, int n_in,
                              void* d_out, int out_size) {
    const float* f   = (const float*)d_in[0];   // [128, 4096]
    const float* nbr = (const float*)d_in[1];   // [4096, 4096]
    const float* wq  = (const float*)d_in[2];   // [128]
    const float* wk  = (const float*)d_in[3];   // [128]
    float* out = (float*)d_out;                 // [4096, 4096]

    build_and_S_kernel<<<NTRI + NBLD, 256>>>(f, nbr, wq, wk);
    fused_T_kernel<<<dim3(NN / 32, NN / 128), 512>>>(out);
}

// round 15
// speedup vs baseline: 1.0749x; 1.0171x over previous
#include <cuda_runtime.h>
#include <cuda_fp16.h>

#define NN 4096
#define FD 128
#define MAXNBR 128
#define NTILE 32                 // 4096/128 S-tiles per dim
#define NTRI  528                // NTILE*(NTILE+1)/2 upper-tri tiles
#define NBLD  1024               // build blocks (4 rows each)

// Scratch (device globals; no cudaMalloc allowed). Hot set = 33 MB, L2-resident.
__device__ __half         g_Sh[(size_t)NN * NN];       // 32 MB fp16 S = exp(f^T C f)
__device__ unsigned short g_idx[(size_t)NN * MAXNBR];  // front/back packed lists
__device__ int            g_cnt0[NN];                  // front-segment count
__device__ int            g_cnt1[NN];                  // back-segment count

// fast exp on the FMA pipe (degree-7 poly of 2^g on [-0.5,0.5]); rel err ~1e-8
__device__ __forceinline__ float fexp(float x) {
    float t = x * 1.4426950408889634f;
    int   ni = __float2int_rn(t);
    float g = t - (float)ni;
    float p =           1.5252734e-5f;
    p = fmaf(p, g,      1.5403530e-4f);
    p = fmaf(p, g,      1.3333558e-3f);
    p = fmaf(p, g,      9.6181291e-3f);
    p = fmaf(p, g,      5.5504109e-2f);
    p = fmaf(p, g,      2.4022651e-1f);
    p = fmaf(p, g,      6.9314718e-1f);
    p = fmaf(p, g,      1.0f);
    return p * __int_as_float((ni + 127) << 23);
}

__device__ __forceinline__ unsigned tf32_rna(float x) {
    unsigned r;
    asm("cvt.rna.tf32.f32 %0, %1;" : "=r"(r) : "f"(x));
    return r;
}

__device__ __forceinline__ void mma_16n8k8(float d[4], const unsigned a[4],
                                           const unsigned b[2]) {
    asm volatile(
        "mma.sync.aligned.m16n8k8.row.col.f32.tf32.tf32.f32 "
        "{%0,%1,%2,%3}, {%4,%5,%6,%7}, {%8,%9}, {%0,%1,%2,%3};"
        : "+f"(d[0]), "+f"(d[1]), "+f"(d[2]), "+f"(d[3])
        : "r"(a[0]), "r"(a[1]), "r"(a[2]), "r"(a[3]), "r"(b[0]), "r"(b[1]));
}

// ---------------------------------------------------------------------------
// build part: neighbor-list scan for 4 rows (2 warps/row, front/back halves),
// ballot fast-path on all-zero float4 groups, MLP 8, plain loads.
// ---------------------------------------------------------------------------
__device__ void build_rows(const float* __restrict__ nbr, int blk) {
    const int warp = threadIdx.x >> 5;        // 0..7
    const int lane = threadIdx.x & 31;
    const int rloc = warp >> 1;
    const int h    = warp & 1;
    const int j    = blk * 4 + rloc;
    const float4* row = (const float4*)(nbr + (size_t)j * NN) + h * 512;
    unsigned short* lst = g_idx + (size_t)j * MAXNBR;
    const unsigned lt = (1u << lane) - 1u;
    const int colbase = h * 2048;

    int base = 0;
    #pragma unroll 1
    for (int step = 0; step < 2; ++step) {
        float4 v[8];
        #pragma unroll
        for (int u = 0; u < 8; ++u)
            v[u] = row[(step * 8 + u) * 32 + lane];      // 8 loads in flight

        #pragma unroll
        for (int u = 0; u < 8; ++u) {
            bool nz = (v[u].x != 0.0f) | (v[u].y != 0.0f) |
                      (v[u].z != 0.0f) | (v[u].w != 0.0f);
            unsigned any = __ballot_sync(0xFFFFFFFFu, nz);
            if (any == 0u) continue;                     // warp-uniform skip

            int col = colbase + ((step * 8 + u) * 32 + lane) * 4;
            unsigned m0 = __ballot_sync(0xFFFFFFFFu, v[u].x != 0.0f);
            unsigned m1 = __ballot_sync(0xFFFFFFFFu, v[u].y != 0.0f);
            unsigned m2 = __ballot_sync(0xFFFFFFFFu, v[u].z != 0.0f);
            unsigned m3 = __ballot_sync(0xFFFFFFFFu, v[u].w != 0.0f);
            int t0 = __popc(m0), t1 = __popc(m1), t2 = __popc(m2), t3 = __popc(m3);
            int p0 = base + __popc(m0 & lt);
            int p1 = base + t0 + __popc(m1 & lt);
            int p2 = base + t0 + t1 + __popc(m2 & lt);
            int p3 = base + t0 + t1 + t2 + __popc(m3 & lt);
            if (h == 0) {
                if ((m0 >> lane) & 1 && p0 < MAXNBR) lst[p0] = (unsigned short)(col + 0);
                if ((m1 >> lane) & 1 && p1 < MAXNBR) lst[p1] = (unsigned short)(col + 1);
                if ((m2 >> lane) & 1 && p2 < MAXNBR) lst[p2] = (unsigned short)(col + 2);
                if ((m3 >> lane) & 1 && p3 < MAXNBR) lst[p3] = (unsigned short)(col + 3);
            } else {
                if ((m0 >> lane) & 1 && p0 < MAXNBR) lst[MAXNBR - 1 - p0] = (unsigned short)(col + 0);
                if ((m1 >> lane) & 1 && p1 < MAXNBR) lst[MAXNBR - 1 - p1] = (unsigned short)(col + 1);
                if ((m2 >> lane) & 1 && p2 < MAXNBR) lst[MAXNBR - 1 - p2] = (unsigned short)(col + 2);
                if ((m3 >> lane) & 1 && p3 < MAXNBR) lst[MAXNBR - 1 - p3] = (unsigned short)(col + 3);
            }
            base += t0 + t1 + t2 + t3;
        }
    }
    if (lane == 0) {
        int c = min(base, MAXNBR);
        if (h == 0) g_cnt0[j] = c; else g_cnt1[j] = c;
    }
}

// ---------------------------------------------------------------------------
// Kernel A (FUSED build + S): blocks [0, NTRI) compute S-tiles (tensor-bound),
// blocks [NTRI, NTRI+NBLD) scan the adjacency (DRAM-bound). S-first ordering.
// ---------------------------------------------------------------------------
__global__ void __launch_bounds__(256, 2)
build_and_S_kernel(const float* __restrict__ f,
                   const float* __restrict__ nbr,
                   const float* __restrict__ wq,
                   const float* __restrict__ wk) {
    if (blockIdx.x >= NTRI) {           // ---- build partition ----
        build_rows(nbr, blockIdx.x - NTRI);
        return;
    }

    // ---- S partition: map linear triangular index -> (ti, tj), tj >= ti ----
    const int t = blockIdx.x;
    int ti = (int)((65.0f - sqrtf(4225.0f - 8.0f * (float)t)) * 0.5f);
    while (ti * (65 - ti) / 2 > t) --ti;
    while ((ti + 1) * (64 - ti) / 2 <= t) ++ti;
    const int tj = ti + (t - ti * (65 - ti) / 2);

    __shared__ float s_raw[2 * 32 * 132];   // As[32][132] | Bs[32][132] (33.8 KB)
    __shared__ float cs[FD];
    float* As = s_raw;
    float* Bs = s_raw + 32 * 132;

    const int tid  = threadIdx.x;
    const int warp = tid >> 5;
    const int lane = tid & 31;
    const int gID  = lane >> 2;
    const int tig  = lane & 3;
    const int wr   = warp >> 2;
    const int wc   = warp & 3;
    const int iw   = wr * 64;
    const int jw   = wc * 32;
    const int i0   = ti * 128;
    const int j0   = tj * 128;

    if (tid < FD) cs[tid] = wq[tid] * wk[tid];
    __syncthreads();

    float acc[4][4][4] = {};

    #pragma unroll 1
    for (int kb = 0; kb < 4; ++kb) {          // 4 chunks of 32 k-slices
        #pragma unroll
        for (int r = 0; r < 4; ++r) {
            int e  = tid + r * 256;
            int d2 = e >> 5;
            int c4 = (e & 31) * 4;
            int d  = kb * 32 + d2;
            float cc = cs[d];
            float4 va = *(const float4*)&f[(size_t)d * NN + i0 + c4];
            unsigned* ap = (unsigned*)&As[d2 * 132 + c4];
            ap[0] = tf32_rna(va.x * cc); ap[1] = tf32_rna(va.y * cc);
            ap[2] = tf32_rna(va.z * cc); ap[3] = tf32_rna(va.w * cc);
            float4 vb = *(const float4*)&f[(size_t)d * NN + j0 + c4];
            unsigned* bp = (unsigned*)&Bs[d2 * 132 + c4];
            bp[0] = tf32_rna(vb.x); bp[1] = tf32_rna(vb.y);
            bp[2] = tf32_rna(vb.z); bp[3] = tf32_rna(vb.w);
        }
        __syncthreads();

        #pragma unroll
        for (int k8 = 0; k8 < 4; ++k8) {
            const int kr0 = k8 * 8 + tig;
            unsigned a[4][4];
            #pragma unroll
            for (int mi = 0; mi < 4; ++mi) {
                int ib = iw + mi * 16 + gID;
                a[mi][0] = ((unsigned*)As)[(kr0    ) * 132 + ib];
                a[mi][1] = ((unsigned*)As)[(kr0    ) * 132 + ib + 8];
                a[mi][2] = ((unsigned*)As)[(kr0 + 4) * 132 + ib];
                a[mi][3] = ((unsigned*)As)[(kr0 + 4) * 132 + ib + 8];
            }
            unsigned b[4][2];
            #pragma unroll
            for (int ni = 0; ni < 4; ++ni) {
                int jb = jw + ni * 8 + gID;
                b[ni][0] = ((unsigned*)Bs)[(kr0    ) * 132 + jb];
                b[ni][1] = ((unsigned*)Bs)[(kr0 + 4) * 132 + jb];
            }
            #pragma unroll
            for (int mi = 0; mi < 4; ++mi)
                #pragma unroll
                for (int ni = 0; ni < 4; ++ni)
                    mma_16n8k8(acc[mi][ni], a[mi], b[ni]);
        }
        __syncthreads();
    }

    #pragma unroll
    for (int mi = 0; mi < 4; ++mi)
        #pragma unroll
        for (int ni = 0; ni < 4; ++ni)
            #pragma unroll
            for (int r = 0; r < 4; ++r)
                acc[mi][ni][r] = fexp(acc[mi][ni][r]);

    // primary tile store: fp16 half2 per fragment pair
    #pragma unroll
    for (int mi = 0; mi < 4; ++mi) {
        #pragma unroll
        for (int h = 0; h < 2; ++h) {
            int row = i0 + iw + mi * 16 + gID + h * 8;
            size_t rbase = (size_t)row * NN + j0;
            #pragma unroll
            for (int ni = 0; ni < 4; ++ni) {
                int col = jw + ni * 8 + 2 * tig;
                __half2 hh = __floats2half2_rn(acc[mi][ni][h * 2 + 0],
                                               acc[mi][ni][h * 2 + 1]);
                *(unsigned*)&g_Sh[rbase + col] = *(unsigned*)&hh;
            }
        }
    }

    // mirror tile (ti != tj): stage 32 tile-cols at a time
    if (ti != tj) {
        float* st = s_raw;   // st[c_local 0..31][row 0..127], stride 132
        #pragma unroll 1
        for (int q = 0; q < 4; ++q) {
            __syncthreads();
            if (wc == q) {
                #pragma unroll
                for (int mi = 0; mi < 4; ++mi)
                    #pragma unroll
                    for (int h = 0; h < 2; ++h) {
                        int rt = iw + mi * 16 + gID + h * 8;
                        #pragma unroll
                        for (int ni = 0; ni < 4; ++ni) {
                            int cl = ni * 8 + 2 * tig;
                            st[(cl + 0) * 132 + rt] = acc[mi][ni][h * 2 + 0];
                            st[(cl + 1) * 132 + rt] = acc[mi][ni][h * 2 + 1];
                        }
                    }
            }
            __syncthreads();
            #pragma unroll
            for (int w = 0; w < 4; ++w) {
                int e4 = tid + w * 256;
                int jl = e4 >> 5;
                int i4 = (e4 & 31) * 4;
                float4 v = *(float4*)&st[jl * 132 + i4];
                size_t rbase = (size_t)(j0 + q * 32 + jl) * NN + i0;
                __half2 h0 = __floats2half2_rn(v.x, v.y);
                __half2 h1 = __floats2half2_rn(v.z, v.w);
                uint2 u = make_uint2(*(unsigned*)&h0, *(unsigned*)&h1);
                *(uint2*)&g_Sh[rbase + i4] = u;
            }
        }
    }
}

// ---------------------------------------------------------------------------
// Kernel B (FUSED gather + divide + transposed write), WARP-PER-J:
// CTA = 16 j's x 256 cols, 512 threads; warp = 1 j (uniform neighbor count,
// zero divergence), thread = (1 j, 8 cols). Same uint4 loads, same
// quad-hadd2 tree (identical per-(j,c) arithmetic as round 14).
// Grid: x = j-blocks (256), y = col-chunks (16) — small L2 footprint/wave.
// ---------------------------------------------------------------------------
__device__ __forceinline__ void addquad(float* acc, const uint4& a, const uint4& b,
                                        const uint4& c, const uint4& d) {
    const __half2* ha = (const __half2*)&a;
    const __half2* hb = (const __half2*)&b;
    const __half2* hc = (const __half2*)&c;
    const __half2* hd = (const __half2*)&d;
    #pragma unroll
    for (int i = 0; i < 4; ++i) {
        __half2 q = __hadd2(__hadd2(ha[i], hb[i]), __hadd2(hc[i], hd[i]));
        float2 p = __half22float2(q);
        acc[2 * i + 0] += p.x;
        acc[2 * i + 1] += p.y;
    }
}
__device__ __forceinline__ void addpair(float* acc, const uint4& x, const uint4& y) {
    const __half2* a = (const __half2*)&x;
    const __half2* b = (const __half2*)&y;
    #pragma unroll
    for (int i = 0; i < 4; ++i) {
        float2 p = __half22float2(__hadd2(a[i], b[i]));
        acc[2 * i + 0] += p.x;
        acc[2 * i + 1] += p.y;
    }
}
__device__ __forceinline__ void addone(float* acc, const uint4& x) {
    const __half2* a = (const __half2*)&x;
    #pragma unroll
    for (int i = 0; i < 4; ++i) {
        float2 p = __half22float2(a[i]);
        acc[2 * i + 0] += p.x;
        acc[2 * i + 1] += p.y;
    }
}

__global__ void __launch_bounds__(512)
fused_T_kernel(float* __restrict__ out) {
    __shared__ unsigned short s_idx[16 * MAXNBR];   // 4 KB
    __shared__ int            s_c0[16];
    __shared__ int            s_c1[16];
    __shared__ float          stage[16 * 257];      // 16.4 KB  [jt][cl]

    const int tid  = threadIdx.x;
    const int lane = tid & 31;
    const int jt   = tid >> 5;                      // warp = j index 0..15
    const int c0   = blockIdx.y * 256;              // col chunk
    const int j0   = blockIdx.x * 16;               // j block

    {
        const uint4* src = (const uint4*)(g_idx + (size_t)j0 * MAXNBR);
        if (tid < 256) ((uint4*)s_idx)[tid] = src[tid];
        if (tid < 16) { s_c0[tid] = g_cnt0[j0 + tid]; s_c1[tid] = g_cnt1[j0 + tid]; }
    }
    __syncthreads();

    const int j  = j0 + jt;
    const int c8 = c0 + lane * 8;
    const unsigned short* lst = &s_idx[jt * MAXNBR];

    // two physical segments: [0, cnt0) and [MAXNBR - cnt1, MAXNBR)
    // both bounds are WARP-UNIFORM -> zero divergence in the gather loops.
    int segLo[2], segHi[2];
    segLo[0] = 0;                   segHi[0] = s_c0[jt];
    segLo[1] = MAXNBR - s_c1[jt];   segHi[1] = MAXNBR;

    float acc[8] = {};
    #pragma unroll
    for (int s = 0; s < 2; ++s) {
        int k = segLo[s];
        const int hi = segHi[s];
        for (; k + 8 <= hi; k += 8) {
            uint4 hv[8];
            #pragma unroll
            for (int u = 0; u < 8; ++u)
                hv[u] = *(const uint4*)&g_Sh[(size_t)lst[k + u] * NN + c8];
            addquad(acc, hv[0], hv[1], hv[2], hv[3]);
            addquad(acc, hv[4], hv[5], hv[6], hv[7]);
        }
        for (; k + 4 <= hi; k += 4) {
            uint4 hv[4];
            #pragma unroll
            for (int u = 0; u < 4; ++u)
                hv[u] = *(const uint4*)&g_Sh[(size_t)lst[k + u] * NN + c8];
            addquad(acc, hv[0], hv[1], hv[2], hv[3]);
        }
        for (; k + 2 <= hi; k += 2) {
            uint4 h0 = *(const uint4*)&g_Sh[(size_t)lst[k + 0] * NN + c8];
            uint4 h1 = *(const uint4*)&g_Sh[(size_t)lst[k + 1] * NN + c8];
            addpair(acc, h0, h1);
        }
        if (k < hi) {
            uint4 h = *(const uint4*)&g_Sh[(size_t)lst[k] * NN + c8];
            addone(acc, h);
        }
    }

    // numerator (fp16), divide, stage [jt][cl]
    uint4 nh = *(const uint4*)&g_Sh[(size_t)j * NN + c8];
    float num[8];
    {
        const __half2* a = (const __half2*)&nh;
        #pragma unroll
        for (int i = 0; i < 4; ++i) {
            float2 p = __half22float2(a[i]);
            num[2 * i + 0] = p.x;
            num[2 * i + 1] = p.y;
        }
    }
    float* sp = &stage[jt * 257 + lane * 8];
    #pragma unroll
    for (int q = 0; q < 8; ++q)
        sp[q] = num[q] / acc[q];
    __syncthreads();

    // transposed write: out rows c0+cl (256 rows), 16 contiguous j's each.
    // idx: cl = idx>>2 (consecutive per 4 lanes), jq = idx&3 -> j4 = jq*4.
    // 4 lanes x 16B = 64B contiguous per out row (2 full 32B sectors).
    #pragma unroll
    for (int w = 0; w < 2; ++w) {
        int idx = tid + w * 512;        // 0..1023
        int cl  = idx >> 2;             // 0..255
        int j4  = (idx & 3) * 4;        // 0,4,8,12
        float4 v = make_float4(stage[(j4 + 0) * 257 + cl],
                               stage[(j4 + 1) * 257 + cl],
                               stage[(j4 + 2) * 257 + cl],
                               stage[(j4 + 3) * 257 + cl]);
        *(float4*)&out[(size_t)(c0 + cl) * NN + j0 + j4] = v;
    }
}

// ---------------------------------------------------------------------------
extern "C" void kernel_launch(void* const* d_in, const int* in_sizes, int n_in,
                              void* d_out, int out_size) {
    const float* f   = (const float*)d_in[0];   // [128, 4096]
    const float* nbr = (const float*)d_in[1];   // [4096, 4096]
    const float* wq  = (const float*)d_in[2];   // [128]
    const float* wk  = (const float*)d_in[3];   // [128]
    float* out = (float*)d_out;                 // [4096, 4096]

    build_and_S_kernel<<<NTRI + NBLD, 256>>>(f, nbr, wq, wk);
    fused_T_kernel<<<dim3(NN / 16, NN / 256), 512>>>(out);
}

// round 16
// speedup vs baseline: 1.0986x; 1.0220x over previous
#include <cuda_runtime.h>
#include <cuda_fp16.h>

#define NN 4096
#define FD 128
#define MAXNBR 128
#define NTILE 32                 // 4096/128 S-tiles per dim
#define NTRI  528                // NTILE*(NTILE+1)/2 upper-tri tiles
#define NBLD  1024               // build blocks (4 rows each)

// Scratch (device globals; no cudaMalloc allowed). Hot set = 33 MB, L2-resident.
__device__ __half         g_Sh[(size_t)NN * NN];       // 32 MB fp16 S = exp(f^T C f)
__device__ unsigned short g_idx[(size_t)NN * MAXNBR];  // front/back packed lists
__device__ int            g_cnt0[NN];                  // front-segment count
__device__ int            g_cnt1[NN];                  // back-segment count

// fast exp on the FMA pipe (degree-7 poly of 2^g on [-0.5,0.5]); rel err ~1e-8
__device__ __forceinline__ float fexp(float x) {
    float t = x * 1.4426950408889634f;
    int   ni = __float2int_rn(t);
    float g = t - (float)ni;
    float p =           1.5252734e-5f;
    p = fmaf(p, g,      1.5403530e-4f);
    p = fmaf(p, g,      1.3333558e-3f);
    p = fmaf(p, g,      9.6181291e-3f);
    p = fmaf(p, g,      5.5504109e-2f);
    p = fmaf(p, g,      2.4022651e-1f);
    p = fmaf(p, g,      6.9314718e-1f);
    p = fmaf(p, g,      1.0f);
    return p * __int_as_float((ni + 127) << 23);
}

// fp16 m16n8k16 MMA: 2x MACs per tensor instruction vs tf32 m16n8k8
__device__ __forceinline__ void mma_16n8k16_f16(float d[4], const unsigned a[4],
                                                const unsigned b[2]) {
    asm volatile(
        "mma.sync.aligned.m16n8k16.row.col.f32.f16.f16.f32 "
        "{%0,%1,%2,%3}, {%4,%5,%6,%7}, {%8,%9}, {%0,%1,%2,%3};"
        : "+f"(d[0]), "+f"(d[1]), "+f"(d[2]), "+f"(d[3])
        : "r"(a[0]), "r"(a[1]), "r"(a[2]), "r"(a[3]), "r"(b[0]), "r"(b[1]));
}

// ---------------------------------------------------------------------------
// build part: neighbor-list scan for 4 rows (2 warps/row, front/back halves),
// ballot fast-path on all-zero float4 groups, MLP 8, plain loads.
// ---------------------------------------------------------------------------
__device__ void build_rows(const float* __restrict__ nbr, int blk) {
    const int warp = threadIdx.x >> 5;        // 0..7
    const int lane = threadIdx.x & 31;
    const int rloc = warp >> 1;
    const int h    = warp & 1;
    const int j    = blk * 4 + rloc;
    const float4* row = (const float4*)(nbr + (size_t)j * NN) + h * 512;
    unsigned short* lst = g_idx + (size_t)j * MAXNBR;
    const unsigned lt = (1u << lane) - 1u;
    const int colbase = h * 2048;

    int base = 0;
    #pragma unroll 1
    for (int step = 0; step < 2; ++step) {
        float4 v[8];
        #pragma unroll
        for (int u = 0; u < 8; ++u)
            v[u] = row[(step * 8 + u) * 32 + lane];      // 8 loads in flight

        #pragma unroll
        for (int u = 0; u < 8; ++u) {
            bool nz = (v[u].x != 0.0f) | (v[u].y != 0.0f) |
                      (v[u].z != 0.0f) | (v[u].w != 0.0f);
            unsigned any = __ballot_sync(0xFFFFFFFFu, nz);
            if (any == 0u) continue;                     // warp-uniform skip

            int col = colbase + ((step * 8 + u) * 32 + lane) * 4;
            unsigned m0 = __ballot_sync(0xFFFFFFFFu, v[u].x != 0.0f);
            unsigned m1 = __ballot_sync(0xFFFFFFFFu, v[u].y != 0.0f);
            unsigned m2 = __ballot_sync(0xFFFFFFFFu, v[u].z != 0.0f);
            unsigned m3 = __ballot_sync(0xFFFFFFFFu, v[u].w != 0.0f);
            int t0 = __popc(m0), t1 = __popc(m1), t2 = __popc(m2), t3 = __popc(m3);
            int p0 = base + __popc(m0 & lt);
            int p1 = base + t0 + __popc(m1 & lt);
            int p2 = base + t0 + t1 + __popc(m2 & lt);
            int p3 = base + t0 + t1 + t2 + __popc(m3 & lt);
            if (h == 0) {
                if ((m0 >> lane) & 1 && p0 < MAXNBR) lst[p0] = (unsigned short)(col + 0);
                if ((m1 >> lane) & 1 && p1 < MAXNBR) lst[p1] = (unsigned short)(col + 1);
                if ((m2 >> lane) & 1 && p2 < MAXNBR) lst[p2] = (unsigned short)(col + 2);
                if ((m3 >> lane) & 1 && p3 < MAXNBR) lst[p3] = (unsigned short)(col + 3);
            } else {
                if ((m0 >> lane) & 1 && p0 < MAXNBR) lst[MAXNBR - 1 - p0] = (unsigned short)(col + 0);
                if ((m1 >> lane) & 1 && p1 < MAXNBR) lst[MAXNBR - 1 - p1] = (unsigned short)(col + 1);
                if ((m2 >> lane) & 1 && p2 < MAXNBR) lst[MAXNBR - 1 - p2] = (unsigned short)(col + 2);
                if ((m3 >> lane) & 1 && p3 < MAXNBR) lst[MAXNBR - 1 - p3] = (unsigned short)(col + 3);
            }
            base += t0 + t1 + t2 + t3;
        }
    }
    if (lane == 0) {
        int c = min(base, MAXNBR);
        if (h == 0) g_cnt0[j] = c; else g_cnt1[j] = c;
    }
}

// ---------------------------------------------------------------------------
// Kernel A (FUSED build + S): blocks [0, NTRI) compute S-tiles via fp16
// m16n8k16 MMA (2x tensor throughput vs tf32 k8); blocks [NTRI, ..) scan the
// adjacency. S-first ordering (build backfills as S tiles finish).
// ---------------------------------------------------------------------------
__global__ void __launch_bounds__(256, 2)
build_and_S_kernel(const float* __restrict__ f,
                   const float* __restrict__ nbr,
                   const float* __restrict__ wq,
                   const float* __restrict__ wk) {
    if (blockIdx.x >= NTRI) {           // ---- build partition ----
        build_rows(nbr, blockIdx.x - NTRI);
        return;
    }

    // ---- S partition: map linear triangular index -> (ti, tj), tj >= ti ----
    const int t = blockIdx.x;
    int ti = (int)((65.0f - sqrtf(4225.0f - 8.0f * (float)t)) * 0.5f);
    while (ti * (65 - ti) / 2 > t) --ti;
    while ((ti + 1) * (64 - ti) / 2 <= t) ++ti;
    const int tj = ti + (t - ti * (65 - ti) / 2);

    // half2 operand tiles As2/Bs2: [k2 0..15][i 0..127], stride 136 words
    // (136 mod 32 = 8 -> LDS pattern 8*tig + i hits 32 distinct banks).
    // Mirror staging (float st[32][132] = 4224 floats) reuses the same buffer.
    __shared__ unsigned s_raw[2 * 16 * 136];   // 17.4 KB
    __shared__ float cs[FD];
    unsigned* As2 = s_raw;
    unsigned* Bs2 = s_raw + 16 * 136;

    const int tid  = threadIdx.x;
    const int warp = tid >> 5;
    const int lane = tid & 31;
    const int gID  = lane >> 2;
    const int tig  = lane & 3;
    const int wr   = warp >> 2;
    const int wc   = warp & 3;
    const int iw   = wr * 64;
    const int jw   = wc * 32;
    const int i0   = ti * 128;
    const int j0   = tj * 128;

    if (tid < FD) cs[tid] = wq[tid] * wk[tid];
    __syncthreads();

    float acc[4][4][4] = {};

    #pragma unroll 1
    for (int kb = 0; kb < 4; ++kb) {          // 4 chunks of 32 k-slices
        // load + pack k-pairs into half2: As2[d2][c] = {c_even*f_even, c_odd*f_odd}
        #pragma unroll
        for (int r = 0; r < 2; ++r) {
            int e  = tid + r * 256;            // 0..511
            int d2 = e >> 5;                   // 0..15 (half2 k-slice)
            int c4 = (e & 31) * 4;             // 0..124
            int d  = kb * 32 + d2 * 2;
            float s0 = cs[d], s1 = cs[d + 1];
            float4 va0 = *(const float4*)&f[(size_t)d * NN + i0 + c4];
            float4 va1 = *(const float4*)&f[(size_t)(d + 1) * NN + i0 + c4];
            __half2 ha[4];
            ha[0] = __floats2half2_rn(va0.x * s0, va1.x * s1);
            ha[1] = __floats2half2_rn(va0.y * s0, va1.y * s1);
            ha[2] = __floats2half2_rn(va0.z * s0, va1.z * s1);
            ha[3] = __floats2half2_rn(va0.w * s0, va1.w * s1);
            *(uint4*)&As2[d2 * 136 + c4] = *(uint4*)ha;

            float4 vb0 = *(const float4*)&f[(size_t)d * NN + j0 + c4];
            float4 vb1 = *(const float4*)&f[(size_t)(d + 1) * NN + j0 + c4];
            __half2 hb[4];
            hb[0] = __floats2half2_rn(vb0.x, vb1.x);
            hb[1] = __floats2half2_rn(vb0.y, vb1.y);
            hb[2] = __floats2half2_rn(vb0.z, vb1.z);
            hb[3] = __floats2half2_rn(vb0.w, vb1.w);
            *(uint4*)&Bs2[d2 * 136 + c4] = *(uint4*)hb;
        }
        __syncthreads();

        // two k16 MMA steps per 32-k chunk (k2 slices 0-7 and 8-15)
        #pragma unroll
        for (int k16 = 0; k16 < 2; ++k16) {
            const int kr = k16 * 8 + tig;      // half2 slice: k = 2*kr, 2*kr+1
            unsigned a[4][4];
            #pragma unroll
            for (int mi = 0; mi < 4; ++mi) {
                int ib = iw + mi * 16 + gID;
                a[mi][0] = As2[(kr    ) * 136 + ib];       // (row g,   k 2t:2t+1)
                a[mi][1] = As2[(kr    ) * 136 + ib + 8];   // (row g+8, k 2t:2t+1)
                a[mi][2] = As2[(kr + 4) * 136 + ib];       // (row g,   k 2t+8:2t+9)
                a[mi][3] = As2[(kr + 4) * 136 + ib + 8];   // (row g+8, k 2t+8:2t+9)
            }
            unsigned b[4][2];
            #pragma unroll
            for (int ni = 0; ni < 4; ++ni) {
                int jb = jw + ni * 8 + gID;
                b[ni][0] = Bs2[(kr    ) * 136 + jb];
                b[ni][1] = Bs2[(kr + 4) * 136 + jb];
            }
            #pragma unroll
            for (int mi = 0; mi < 4; ++mi)
                #pragma unroll
                for (int ni = 0; ni < 4; ++ni)
                    mma_16n8k16_f16(acc[mi][ni], a[mi], b[ni]);
        }
        __syncthreads();
    }

    #pragma unroll
    for (int mi = 0; mi < 4; ++mi)
        #pragma unroll
        for (int ni = 0; ni < 4; ++ni)
            #pragma unroll
            for (int r = 0; r < 4; ++r)
                acc[mi][ni][r] = fexp(acc[mi][ni][r]);

    // primary tile store: fp16 half2 per fragment pair
    #pragma unroll
    for (int mi = 0; mi < 4; ++mi) {
        #pragma unroll
        for (int h = 0; h < 2; ++h) {
            int row = i0 + iw + mi * 16 + gID + h * 8;
            size_t rbase = (size_t)row * NN + j0;
            #pragma unroll
            for (int ni = 0; ni < 4; ++ni) {
                int col = jw + ni * 8 + 2 * tig;
                __half2 hh = __floats2half2_rn(acc[mi][ni][h * 2 + 0],
                                               acc[mi][ni][h * 2 + 1]);
                *(unsigned*)&g_Sh[rbase + col] = *(unsigned*)&hh;
            }
        }
    }

    // mirror tile (ti != tj): stage 32 tile-cols at a time (reuse s_raw)
    if (ti != tj) {
        float* st = (float*)s_raw;   // st[c_local 0..31][row 0..127], stride 132
        #pragma unroll 1
        for (int q = 0; q < 4; ++q) {
            __syncthreads();
            if (wc == q) {
                #pragma unroll
                for (int mi = 0; mi < 4; ++mi)
                    #pragma unroll
                    for (int h = 0; h < 2; ++h) {
                        int rt = iw + mi * 16 + gID + h * 8;
                        #pragma unroll
                        for (int ni = 0; ni < 4; ++ni) {
                            int cl = ni * 8 + 2 * tig;
                            st[(cl + 0) * 132 + rt] = acc[mi][ni][h * 2 + 0];
                            st[(cl + 1) * 132 + rt] = acc[mi][ni][h * 2 + 1];
                        }
                    }
            }
            __syncthreads();
            #pragma unroll
            for (int w = 0; w < 4; ++w) {
                int e4 = tid + w * 256;
                int jl = e4 >> 5;
                int i4 = (e4 & 31) * 4;
                float4 v = *(float4*)&st[jl * 132 + i4];
                size_t rbase = (size_t)(j0 + q * 32 + jl) * NN + i0;
                __half2 h0 = __floats2half2_rn(v.x, v.y);
                __half2 h1 = __floats2half2_rn(v.z, v.w);
                uint2 u = make_uint2(*(unsigned*)&h0, *(unsigned*)&h1);
                *(uint2*)&g_Sh[rbase + i4] = u;
            }
        }
    }
}

// ---------------------------------------------------------------------------
// Kernel B (FUSED gather + divide + transposed write), WARP-PER-J:
// CTA = 16 j's x 256 cols, 512 threads; warp = 1 j (uniform neighbor count),
// thread = (1 j, 8 cols). uint4 loads, quad-hadd2 tree.  (round-15, measured)
// ---------------------------------------------------------------------------
__device__ __forceinline__ void addquad(float* acc, const uint4& a, const uint4& b,
                                        const uint4& c, const uint4& d) {
    const __half2* ha = (const __half2*)&a;
    const __half2* hb = (const __half2*)&b;
    const __half2* hc = (const __half2*)&c;
    const __half2* hd = (const __half2*)&d;
    #pragma unroll
    for (int i = 0; i < 4; ++i) {
        __half2 q = __hadd2(__hadd2(ha[i], hb[i]), __hadd2(hc[i], hd[i]));
        float2 p = __half22float2(q);
        acc[2 * i + 0] += p.x;
        acc[2 * i + 1] += p.y;
    }
}
__device__ __forceinline__ void addpair(float* acc, const uint4& x, const uint4& y) {
    const __half2* a = (const __half2*)&x;
    const __half2* b = (const __half2*)&y;
    #pragma unroll
    for (int i = 0; i < 4; ++i) {
        float2 p = __half22float2(__hadd2(a[i], b[i]));
        acc[2 * i + 0] += p.x;
        acc[2 * i + 1] += p.y;
    }
}
__device__ __forceinline__ void addone(float* acc, const uint4& x) {
    const __half2* a = (const __half2*)&x;
    #pragma unroll
    for (int i = 0; i < 4; ++i) {
        float2 p = __half22float2(a[i]);
        acc[2 * i + 0] += p.x;
        acc[2 * i + 1] += p.y;
    }
}

__global__ void __launch_bounds__(512)
fused_T_kernel(float* __restrict__ out) {
    __shared__ unsigned short s_idx[16 * MAXNBR];   // 4 KB
    __shared__ int            s_c0[16];
    __shared__ int            s_c1[16];
    __shared__ float          stage[16 * 257];      // 16.4 KB  [jt][cl]

    const int tid  = threadIdx.x;
    const int lane = tid & 31;
    const int jt   = tid >> 5;                      // warp = j index 0..15
    const int c0   = blockIdx.y * 256;              // col chunk
    const int j0   = blockIdx.x * 16;               // j block

    {
        const uint4* src = (const uint4*)(g_idx + (size_t)j0 * MAXNBR);
        if (tid < 256) ((uint4*)s_idx)[tid] = src[tid];
        if (tid < 16) { s_c0[tid] = g_cnt0[j0 + tid]; s_c1[tid] = g_cnt1[j0 + tid]; }
    }
    __syncthreads();

    const int j  = j0 + jt;
    const int c8 = c0 + lane * 8;
    const unsigned short* lst = &s_idx[jt * MAXNBR];

    int segLo[2], segHi[2];
    segLo[0] = 0;                   segHi[0] = s_c0[jt];
    segLo[1] = MAXNBR - s_c1[jt];   segHi[1] = MAXNBR;

    float acc[8] = {};
    #pragma unroll
    for (int s = 0; s < 2; ++s) {
        int k = segLo[s];
        const int hi = segHi[s];
        for (; k + 8 <= hi; k += 8) {
            uint4 hv[8];
            #pragma unroll
            for (int u = 0; u < 8; ++u)
                hv[u] = *(const uint4*)&g_Sh[(size_t)lst[k + u] * NN + c8];
            addquad(acc, hv[0], hv[1], hv[2], hv[3]);
            addquad(acc, hv[4], hv[5], hv[6], hv[7]);
        }
        for (; k + 4 <= hi; k += 4) {
            uint4 hv[4];
            #pragma unroll
            for (int u = 0; u < 4; ++u)
                hv[u] = *(const uint4*)&g_Sh[(size_t)lst[k + u] * NN + c8];
            addquad(acc, hv[0], hv[1], hv[2], hv[3]);
        }
        for (; k + 2 <= hi; k += 2) {
            uint4 h0 = *(const uint4*)&g_Sh[(size_t)lst[k + 0] * NN + c8];
            uint4 h1 = *(const uint4*)&g_Sh[(size_t)lst[k + 1] * NN + c8];
            addpair(acc, h0, h1);
        }
        if (k < hi) {
            uint4 h = *(const uint4*)&g_Sh[(size_t)lst[k] * NN + c8];
            addone(acc, h);
        }
    }

    // numerator (fp16), divide, stage [jt][cl]
    uint4 nh = *(const uint4*)&g_Sh[(size_t)j * NN + c8];
    float num[8];
    {
        const __half2* a = (const __half2*)&nh;
        #pragma unroll
        for (int i = 0; i < 4; ++i) {
            float2 p = __half22float2(a[i]);
            num[2 * i + 0] = p.x;
            num[2 * i + 1] = p.y;
        }
    }
    float* sp = &stage[jt * 257 + lane * 8];
    #pragma unroll
    for (int q = 0; q < 8; ++q)
        sp[q] = num[q] / acc[q];
    __syncthreads();

    // transposed write: out rows c0+cl (256 rows), 16 contiguous j's each
    #pragma unroll
    for (int w = 0; w < 2; ++w) {
        int idx = tid + w * 512;
        int cl  = idx >> 2;
        int j4  = (idx & 3) * 4;
        float4 v = make_float4(stage[(j4 + 0) * 257 + cl],
                               stage[(j4 + 1) * 257 + cl],
                               stage[(j4 + 2) * 257 + cl],
                               stage[(j4 + 3) * 257 + cl]);
        *(float4*)&out[(size_t)(c0 + cl) * NN + j0 + j4] = v;
    }
}

// ---------------------------------------------------------------------------
extern "C" void kernel_launch(void* const* d_in, const int* in_sizes, int n_in,
                              void* d_out, int out_size) {
    const float* f   = (const float*)d_in[0];   // [128, 4096]
    const float* nbr = (const float*)d_in[1];   // [4096, 4096]
    const float* wq  = (const float*)d_in[2];   // [128]
    const float* wk  = (const float*)d_in[3];   // [128]
    float* out = (float*)d_out;                 // [4096, 4096]

    build_and_S_kernel<<<NTRI + NBLD, 256>>>(f, nbr, wq, wk);
    fused_T_kernel<<<dim3(NN / 16, NN / 256), 512>>>(out);
}

// round 17
// speedup vs baseline: 1.1202x; 1.0197x over previous
#include <cuda_runtime.h>
#include <cuda_fp16.h>

#define NN 4096
#define FD 128
#define MAXNBR 128
#define NTILE 32                 // 4096/128 S-tiles per dim
#define NTRI  528                // NTILE*(NTILE+1)/2 upper-tri tiles
#define NBLD  1024               // build blocks (4 rows each)

// Scratch (device globals; no cudaMalloc allowed). Hot set = 37 MB, L2-resident.
__device__ __half         g_Sh[(size_t)NN * NN];       // 32 MB fp16 S = exp(f^T C f)
__device__ __half2        g_fp [64 * NN];              // 2 MB  {f[2d],f[2d+1]} pairs
__device__ __half2        g_cfp[64 * NN];              // 2 MB  scaled pairs (c*f)
__device__ unsigned short g_idx[(size_t)NN * MAXNBR];  // front/back packed lists
__device__ int            g_cnt0[NN];                  // front-segment count
__device__ int            g_cnt1[NN];                  // back-segment count

// fast exp on the FMA pipe (degree-7 poly of 2^g on [-0.5,0.5]); rel err ~1e-8
__device__ __forceinline__ float fexp(float x) {
    float t = x * 1.4426950408889634f;
    int   ni = __float2int_rn(t);
    float g = t - (float)ni;
    float p =           1.5252734e-5f;
    p = fmaf(p, g,      1.5403530e-4f);
    p = fmaf(p, g,      1.3333558e-3f);
    p = fmaf(p, g,      9.6181291e-3f);
    p = fmaf(p, g,      5.5504109e-2f);
    p = fmaf(p, g,      2.4022651e-1f);
    p = fmaf(p, g,      6.9314718e-1f);
    p = fmaf(p, g,      1.0f);
    return p * __int_as_float((ni + 127) << 23);
}

// fp16 m16n8k16 MMA: 2x MACs per tensor instruction vs tf32 m16n8k8
__device__ __forceinline__ void mma_16n8k16_f16(float d[4], const unsigned a[4],
                                                const unsigned b[2]) {
    asm volatile(
        "mma.sync.aligned.m16n8k16.row.col.f32.f16.f16.f32 "
        "{%0,%1,%2,%3}, {%4,%5,%6,%7}, {%8,%9}, {%0,%1,%2,%3};"
        : "+f"(d[0]), "+f"(d[1]), "+f"(d[2]), "+f"(d[3])
        : "r"(a[0]), "r"(a[1]), "r"(a[2]), "r"(a[3]), "r"(b[0]), "r"(b[1]));
}

// ---------------------------------------------------------------------------
// Kernel P: pre-pack f into half2 k-pair tables (plain + scaled).
// One CTA per d2 (64 CTAs), same __floats2half2_rn arithmetic the S loader
// used before — values bit-identical, computed once instead of per tile.
// ---------------------------------------------------------------------------
__global__ void pack_f_kernel(const float* __restrict__ f,
                              const float* __restrict__ wq,
                              const float* __restrict__ wk) {
    const int d2 = blockIdx.x;
    const int d  = d2 * 2;
    const float s0 = wq[d] * wk[d];
    const float s1 = wq[d + 1] * wk[d + 1];
    const float4* r0 = (const float4*)(f + (size_t)d * NN);
    const float4* r1 = (const float4*)(f + (size_t)(d + 1) * NN);
    uint4* fp  = (uint4*)g_fp;
    uint4* cfp = (uint4*)g_cfp;

    for (int s = threadIdx.x; s < NN / 4; s += 256) {
        float4 a = r0[s];
        float4 b = r1[s];
        __half2 h[4];
        h[0] = __floats2half2_rn(a.x, b.x);
        h[1] = __floats2half2_rn(a.y, b.y);
        h[2] = __floats2half2_rn(a.z, b.z);
        h[3] = __floats2half2_rn(a.w, b.w);
        fp[d2 * (NN / 4) + s] = *(uint4*)h;
        __half2 hc[4];
        hc[0] = __floats2half2_rn(a.x * s0, b.x * s1);
        hc[1] = __floats2half2_rn(a.y * s0, b.y * s1);
        hc[2] = __floats2half2_rn(a.z * s0, b.z * s1);
        hc[3] = __floats2half2_rn(a.w * s0, b.w * s1);
        cfp[d2 * (NN / 4) + s] = *(uint4*)hc;
    }
}

// ---------------------------------------------------------------------------
// build part: neighbor-list scan for 4 rows (2 warps/row, front/back halves),
// ballot fast-path on all-zero float4 groups, MLP 8, plain loads.
// ---------------------------------------------------------------------------
__device__ void build_rows(const float* __restrict__ nbr, int blk) {
    const int warp = threadIdx.x >> 5;        // 0..7
    const int lane = threadIdx.x & 31;
    const int rloc = warp >> 1;
    const int h    = warp & 1;
    const int j    = blk * 4 + rloc;
    const float4* row = (const float4*)(nbr + (size_t)j * NN) + h * 512;
    unsigned short* lst = g_idx + (size_t)j * MAXNBR;
    const unsigned lt = (1u << lane) - 1u;
    const int colbase = h * 2048;

    int base = 0;
    #pragma unroll 1
    for (int step = 0; step < 2; ++step) {
        float4 v[8];
        #pragma unroll
        for (int u = 0; u < 8; ++u)
            v[u] = row[(step * 8 + u) * 32 + lane];      // 8 loads in flight

        #pragma unroll
        for (int u = 0; u < 8; ++u) {
            bool nz = (v[u].x != 0.0f) | (v[u].y != 0.0f) |
                      (v[u].z != 0.0f) | (v[u].w != 0.0f);
            unsigned any = __ballot_sync(0xFFFFFFFFu, nz);
            if (any == 0u) continue;                     // warp-uniform skip

            int col = colbase + ((step * 8 + u) * 32 + lane) * 4;
            unsigned m0 = __ballot_sync(0xFFFFFFFFu, v[u].x != 0.0f);
            unsigned m1 = __ballot_sync(0xFFFFFFFFu, v[u].y != 0.0f);
            unsigned m2 = __ballot_sync(0xFFFFFFFFu, v[u].z != 0.0f);
            unsigned m3 = __ballot_sync(0xFFFFFFFFu, v[u].w != 0.0f);
            int t0 = __popc(m0), t1 = __popc(m1), t2 = __popc(m2), t3 = __popc(m3);
            int p0 = base + __popc(m0 & lt);
            int p1 = base + t0 + __popc(m1 & lt);
            int p2 = base + t0 + t1 + __popc(m2 & lt);
            int p3 = base + t0 + t1 + t2 + __popc(m3 & lt);
            if (h == 0) {
                if ((m0 >> lane) & 1 && p0 < MAXNBR) lst[p0] = (unsigned short)(col + 0);
                if ((m1 >> lane) & 1 && p1 < MAXNBR) lst[p1] = (unsigned short)(col + 1);
                if ((m2 >> lane) & 1 && p2 < MAXNBR) lst[p2] = (unsigned short)(col + 2);
                if ((m3 >> lane) & 1 && p3 < MAXNBR) lst[p3] = (unsigned short)(col + 3);
            } else {
                if ((m0 >> lane) & 1 && p0 < MAXNBR) lst[MAXNBR - 1 - p0] = (unsigned short)(col + 0);
                if ((m1 >> lane) & 1 && p1 < MAXNBR) lst[MAXNBR - 1 - p1] = (unsigned short)(col + 1);
                if ((m2 >> lane) & 1 && p2 < MAXNBR) lst[MAXNBR - 1 - p2] = (unsigned short)(col + 2);
                if ((m3 >> lane) & 1 && p3 < MAXNBR) lst[MAXNBR - 1 - p3] = (unsigned short)(col + 3);
            }
            base += t0 + t1 + t2 + t3;
        }
    }
    if (lane == 0) {
        int c = min(base, MAXNBR);
        if (h == 0) g_cnt0[j] = c; else g_cnt1[j] = c;
    }
}

// ---------------------------------------------------------------------------
// Kernel A (FUSED build + S): blocks [0, NTRI) compute S-tiles via fp16
// m16n8k16 MMA with a pure-copy loader (pre-packed half2 operands);
// blocks [NTRI, ..) scan the adjacency. S-first ordering.
// ---------------------------------------------------------------------------
__global__ void __launch_bounds__(256, 2)
build_and_S_kernel(const float* __restrict__ nbr) {
    if (blockIdx.x >= NTRI) {           // ---- build partition ----
        build_rows(nbr, blockIdx.x - NTRI);
        return;
    }

    // ---- S partition: map linear triangular index -> (ti, tj), tj >= ti ----
    const int t = blockIdx.x;
    int ti = (int)((65.0f - sqrtf(4225.0f - 8.0f * (float)t)) * 0.5f);
    while (ti * (65 - ti) / 2 > t) --ti;
    while ((ti + 1) * (64 - ti) / 2 <= t) ++ti;
    const int tj = ti + (t - ti * (65 - ti) / 2);

    // half2 operand tiles As2/Bs2: [k2 0..15][col 0..127], stride 136 words.
    // Mirror staging (float st[32][132] = 4224 floats) reuses the same buffer.
    __shared__ unsigned s_raw[2 * 16 * 136];   // 17.4 KB
    unsigned* As2 = s_raw;
    unsigned* Bs2 = s_raw + 16 * 136;

    const int tid  = threadIdx.x;
    const int warp = tid >> 5;
    const int lane = tid & 31;
    const int gID  = lane >> 2;
    const int tig  = lane & 3;
    const int wr   = warp >> 2;
    const int wc   = warp & 3;
    const int iw   = wr * 64;
    const int jw   = wc * 32;
    const int i0   = ti * 128;
    const int j0   = tj * 128;

    const uint4* fp4  = (const uint4*)g_fp;    // [d2][col/4] uint4 (4 cols each)
    const uint4* cfp4 = (const uint4*)g_cfp;

    float acc[4][4][4] = {};

    #pragma unroll 1
    for (int kb = 0; kb < 4; ++kb) {          // 4 chunks of 32 k-slices
        // pure-copy loader: 2 uint4 per slot (As2 from cfp, Bs2 from fp)
        #pragma unroll
        for (int r = 0; r < 2; ++r) {
            int e   = tid + r * 256;           // 0..511
            int d2l = e >> 5;                  // 0..15
            int c4  = (e & 31) * 4;            // 0..124
            int d2g = kb * 16 + d2l;
            *(uint4*)&As2[d2l * 136 + c4] = cfp4[d2g * (NN / 4) + ((i0 + c4) >> 2)];
            *(uint4*)&Bs2[d2l * 136 + c4] = fp4 [d2g * (NN / 4) + ((j0 + c4) >> 2)];
        }
        __syncthreads();

        // two k16 MMA steps per 32-k chunk (k2 slices 0-7 and 8-15)
        #pragma unroll
        for (int k16 = 0; k16 < 2; ++k16) {
            const int kr = k16 * 8 + tig;      // half2 slice: k = 2*kr, 2*kr+1
            unsigned a[4][4];
            #pragma unroll
            for (int mi = 0; mi < 4; ++mi) {
                int ib = iw + mi * 16 + gID;
                a[mi][0] = As2[(kr    ) * 136 + ib];
                a[mi][1] = As2[(kr    ) * 136 + ib + 8];
                a[mi][2] = As2[(kr + 4) * 136 + ib];
                a[mi][3] = As2[(kr + 4) * 136 + ib + 8];
            }
            unsigned b[4][2];
            #pragma unroll
            for (int ni = 0; ni < 4; ++ni) {
                int jb = jw + ni * 8 + gID;
                b[ni][0] = Bs2[(kr    ) * 136 + jb];
                b[ni][1] = Bs2[(kr + 4) * 136 + jb];
            }
            #pragma unroll
            for (int mi = 0; mi < 4; ++mi)
                #pragma unroll
                for (int ni = 0; ni < 4; ++ni)
                    mma_16n8k16_f16(acc[mi][ni], a[mi], b[ni]);
        }
        __syncthreads();
    }

    #pragma unroll
    for (int mi = 0; mi < 4; ++mi)
        #pragma unroll
        for (int ni = 0; ni < 4; ++ni)
            #pragma unroll
            for (int r = 0; r < 4; ++r)
                acc[mi][ni][r] = fexp(acc[mi][ni][r]);

    // primary tile store: fp16 half2 per fragment pair
    #pragma unroll
    for (int mi = 0; mi < 4; ++mi) {
        #pragma unroll
        for (int h = 0; h < 2; ++h) {
            int row = i0 + iw + mi * 16 + gID + h * 8;
            size_t rbase = (size_t)row * NN + j0;
            #pragma unroll
            for (int ni = 0; ni < 4; ++ni) {
                int col = jw + ni * 8 + 2 * tig;
                __half2 hh = __floats2half2_rn(acc[mi][ni][h * 2 + 0],
                                               acc[mi][ni][h * 2 + 1]);
                *(unsigned*)&g_Sh[rbase + col] = *(unsigned*)&hh;
            }
        }
    }

    // mirror tile (ti != tj): stage 32 tile-cols at a time (reuse s_raw)
    if (ti != tj) {
        float* st = (float*)s_raw;   // st[c_local 0..31][row 0..127], stride 132
        #pragma unroll 1
        for (int q = 0; q < 4; ++q) {
            __syncthreads();
            if (wc == q) {
                #pragma unroll
                for (int mi = 0; mi < 4; ++mi)
                    #pragma unroll
                    for (int h = 0; h < 2; ++h) {
                        int rt = iw + mi * 16 + gID + h * 8;
                        #pragma unroll
                        for (int ni = 0; ni < 4; ++ni) {
                            int cl = ni * 8 + 2 * tig;
                            st[(cl + 0) * 132 + rt] = acc[mi][ni][h * 2 + 0];
                            st[(cl + 1) * 132 + rt] = acc[mi][ni][h * 2 + 1];
                        }
                    }
            }
            __syncthreads();
            #pragma unroll
            for (int w = 0; w < 4; ++w) {
                int e4 = tid + w * 256;
                int jl = e4 >> 5;
                int i4 = (e4 & 31) * 4;
                float4 v = *(float4*)&st[jl * 132 + i4];
                size_t rbase = (size_t)(j0 + q * 32 + jl) * NN + i0;
                __half2 h0 = __floats2half2_rn(v.x, v.y);
                __half2 h1 = __floats2half2_rn(v.z, v.w);
                uint2 u = make_uint2(*(unsigned*)&h0, *(unsigned*)&h1);
                *(uint2*)&g_Sh[rbase + i4] = u;
            }
        }
    }
}

// ---------------------------------------------------------------------------
// Kernel B (FUSED gather + divide + transposed write), WARP-PER-J:
// CTA = 16 j's x 256 cols, 512 threads; warp = 1 j (uniform neighbor count),
// thread = (1 j, 8 cols). uint4 loads, quad-hadd2 tree.  (round-15, measured)
// ---------------------------------------------------------------------------
__device__ __forceinline__ void addquad(float* acc, const uint4& a, const uint4& b,
                                        const uint4& c, const uint4& d) {
    const __half2* ha = (const __half2*)&a;
    const __half2* hb = (const __half2*)&b;
    const __half2* hc = (const __half2*)&c;
    const __half2* hd = (const __half2*)&d;
    #pragma unroll
    for (int i = 0; i < 4; ++i) {
        __half2 q = __hadd2(__hadd2(ha[i], hb[i]), __hadd2(hc[i], hd[i]));
        float2 p = __half22float2(q);
        acc[2 * i + 0] += p.x;
        acc[2 * i + 1] += p.y;
    }
}
__device__ __forceinline__ void addpair(float* acc, const uint4& x, const uint4& y) {
    const __half2* a = (const __half2*)&x;
    const __half2* b = (const __half2*)&y;
    #pragma unroll
    for (int i = 0; i < 4; ++i) {
        float2 p = __half22float2(__hadd2(a[i], b[i]));
        acc[2 * i + 0] += p.x;
        acc[2 * i + 1] += p.y;
    }
}
__device__ __forceinline__ void addone(float* acc, const uint4& x) {
    const __half2* a = (const __half2*)&x;
    #pragma unroll
    for (int i = 0; i < 4; ++i) {
        float2 p = __half22float2(a[i]);
        acc[2 * i + 0] += p.x;
        acc[2 * i + 1] += p.y;
    }
}

__global__ void __launch_bounds__(512)
fused_T_kernel(float* __restrict__ out) {
    __shared__ unsigned short s_idx[16 * MAXNBR];   // 4 KB
    __shared__ int            s_c0[16];
    __shared__ int            s_c1[16];
    __shared__ float          stage[16 * 257];      // 16.4 KB  [jt][cl]

    const int tid  = threadIdx.x;
    const int lane = tid & 31;
    const int jt   = tid >> 5;                      // warp = j index 0..15
    const int c0   = blockIdx.y * 256;              // col chunk
    const int j0   = blockIdx.x * 16;               // j block

    {
        const uint4* src = (const uint4*)(g_idx + (size_t)j0 * MAXNBR);
        if (tid < 256) ((uint4*)s_idx)[tid] = src[tid];
        if (tid < 16) { s_c0[tid] = g_cnt0[j0 + tid]; s_c1[tid] = g_cnt1[j0 + tid]; }
    }
    __syncthreads();

    const int j  = j0 + jt;
    const int c8 = c0 + lane * 8;
    const unsigned short* lst = &s_idx[jt * MAXNBR];

    int segLo[2], segHi[2];
    segLo[0] = 0;                   segHi[0] = s_c0[jt];
    segLo[1] = MAXNBR - s_c1[jt];   segHi[1] = MAXNBR;

    float acc[8] = {};
    #pragma unroll
    for (int s = 0; s < 2; ++s) {
        int k = segLo[s];
        const int hi = segHi[s];
        for (; k + 8 <= hi; k += 8) {
            uint4 hv[8];
            #pragma unroll
            for (int u = 0; u < 8; ++u)
                hv[u] = *(const uint4*)&g_Sh[(size_t)lst[k + u] * NN + c8];
            addquad(acc, hv[0], hv[1], hv[2], hv[3]);
            addquad(acc, hv[4], hv[5], hv[6], hv[7]);
        }
        for (; k + 4 <= hi; k += 4) {
            uint4 hv[4];
            #pragma unroll
            for (int u = 0; u < 4; ++u)
                hv[u] = *(const uint4*)&g_Sh[(size_t)lst[k + u] * NN + c8];
            addquad(acc, hv[0], hv[1], hv[2], hv[3]);
        }
        for (; k + 2 <= hi; k += 2) {
            uint4 h0 = *(const uint4*)&g_Sh[(size_t)lst[k + 0] * NN + c8];
            uint4 h1 = *(const uint4*)&g_Sh[(size_t)lst[k + 1] * NN + c8];
            addpair(acc, h0, h1);
        }
        if (k < hi) {
            uint4 h = *(const uint4*)&g_Sh[(size_t)lst[k] * NN + c8];
            addone(acc, h);
        }
    }

    // numerator (fp16), divide, stage [jt][cl]
    uint4 nh = *(const uint4*)&g_Sh[(size_t)j * NN + c8];
    float num[8];
    {
        const __half2* a = (const __half2*)&nh;
        #pragma unroll
        for (int i = 0; i < 4; ++i) {
            float2 p = __half22float2(a[i]);
            num[2 * i + 0] = p.x;
            num[2 * i + 1] = p.y;
        }
    }
    float* sp = &stage[jt * 257 + lane * 8];
    #pragma unroll
    for (int q = 0; q < 8; ++q)
        sp[q] = num[q] / acc[q];
    __syncthreads();

    // transposed write: out rows c0+cl (256 rows), 16 contiguous j's each
    #pragma unroll
    for (int w = 0; w < 2; ++w) {
        int idx = tid + w * 512;
        int cl  = idx >> 2;
        int j4  = (idx & 3) * 4;
        float4 v = make_float4(stage[(j4 + 0) * 257 + cl],
                               stage[(j4 + 1) * 257 + cl],
                               stage[(j4 + 2) * 257 + cl],
                               stage[(j4 + 3) * 257 + cl]);
        *(float4*)&out[(size_t)(c0 + cl) * NN + j0 + j4] = v;
    }
}

// ---------------------------------------------------------------------------
extern "C" void kernel_launch(void* const* d_in, const int* in_sizes, int n_in,
                              void* d_out, int out_size) {
    const float* f   = (const float*)d_in[0];   // [128, 4096]
    const float* nbr = (const float*)d_in[1];   // [4096, 4096]
    const float* wq  = (const float*)d_in[2];   // [128]
    const float* wk  = (const float*)d_in[3];   // [128]
    float* out = (float*)d_out;                 // [4096, 4096]

    pack_f_kernel<<<64, 256>>>(f, wq, wk);
    build_and_S_kernel<<<NTRI + NBLD, 256>>>(nbr);
    fused_T_kernel<<<dim3(NN / 16, NN / 256), 512>>>(out);
}